// round 13
// baseline (speedup 1.0000x reference)
#include <cuda_runtime.h>
#include <cuda_fp16.h>
#include <cstdint>
#include <cstddef>

static constexpr int BB = 8, SSQ = 4096, DIN = 256, HH = 512;
static constexpr int M = BB * SSQ;        // 32768
static constexpr int KE = 256;            // single fp16 term
static constexpr int NG = 4 * HH;         // 2048
static constexpr float EPSF = 1e-6f;
static constexpr int LCH = 128, NCH = SSQ / LCH;   // 32 chunks of 128

static constexpr int PAD = 40;            // smem row stride (halfs); LDSM conflict-free
static constexpr int BM = 256, BN = 128, BK = 32;
static constexpr int NKT = KE / BK;       // 8
static constexpr int A_BYTES = BM * PAD * 2;   // 20480
static constexpr int B_BYTES = BN * PAD * 2;   // 10240
static constexpr int STGB = A_BYTES + B_BYTES; // 30720
static constexpr int NSTAGE = 3;
static constexpr int SMEM_DYN = NSTAGE * STGB; // 92160

static __device__ __half g_Ah[(size_t)M * KE];     // 16 MB
static __device__ __half g_Bh[(size_t)NG * KE];    // 1 MB
// gates, gate-interleaved: element (m, h) = 4 halfs (i,f,o,z) at g_Gh[m*NG + h*4]
static __device__ __half g_Gh[(size_t)M * NG];     // 128 MB

__device__ __forceinline__ uint32_t smem_u32(const void* p) {
    uint32_t a;
    asm("{ .reg .u64 t; cvta.to.shared.u64 t, %1; cvt.u32.u64 %0, t; }" : "=r"(a) : "l"(p));
    return a;
}

// ---------------- prep A: fp16(x), row-major K-contig ----------------
__global__ void xl_prepA(const float* __restrict__ x) {
    int gid = blockIdx.x * blockDim.x + threadIdx.x;       // M*64 threads, 4 k each
    int j = gid & 63, m = gid >> 6;
    int k = j * 4;
    float4 v = *reinterpret_cast<const float4*>(x + (size_t)m * DIN + k);
    __half h[4] = {__float2half_rn(v.x), __float2half_rn(v.y),
                   __float2half_rn(v.z), __float2half_rn(v.w)};
    *reinterpret_cast<uint2*>(g_Ah + (size_t)m * KE + k) = *reinterpret_cast<uint2*>(h);
}

// ------- prep B: row n' = h*4 + gate; fp16(W) -------
__global__ void xl_prepB(const float* __restrict__ Wi, const float* __restrict__ Wf,
                         const float* __restrict__ Wo, const float* __restrict__ Wz) {
    int gid = blockIdx.x * blockDim.x + threadIdx.x;       // NG*64 threads, 4 k each
    int j = gid & 63, n = gid >> 6;
    int k = j * 4;
    int g = n & 3, h = n >> 2;
    const float* W = (g == 0) ? Wi : (g == 1) ? Wf : (g == 2) ? Wo : Wz;
    __half out[4];
#pragma unroll
    for (int t = 0; t < 4; t++)
        out[t] = __float2half_rn(W[(size_t)(k + t) * HH + h]);
    *reinterpret_cast<uint2*>(g_Bh + (size_t)n * KE + k) = *reinterpret_cast<uint2*>(out);
}

// ------ GEMM 256x128 (ldmatrix + 3-stage cp.async, single-sync) + epilogue ---
#define LDSM_X4(r, addr) \
    asm volatile("ldmatrix.sync.aligned.m8n8.x4.shared.b16 {%0,%1,%2,%3}, [%4];" \
        : "=r"((r)[0]), "=r"((r)[1]), "=r"((r)[2]), "=r"((r)[3]) : "r"(addr))

__global__ __launch_bounds__(512, 1) void xl_gemm(const float* __restrict__ bi, const float* __restrict__ bfg,
                                                  const float* __restrict__ bo, const float* __restrict__ bz) {
    extern __shared__ char smem[];
    const uint32_t sbase = smem_u32(smem);
    const int tid = threadIdx.x, lane = tid & 31, wid = tid >> 5;   // 16 warps
    const int bm = blockIdx.y * BM, bn = blockIdx.x * BN;
    const int warp_m = (wid & 3) * 64, warp_n = (wid >> 2) * 32;
    const int grp = lane >> 2, tq = lane & 3;

    float acc[4][4][4];
#pragma unroll
    for (int a = 0; a < 4; a++)
#pragma unroll
        for (int b = 0; b < 4; b++)
#pragma unroll
            for (int c = 0; c < 4; c++) acc[a][b][c] = 0.f;

    const int rsel = (lane & 7) + ((lane >> 3) & 1) * 8;
    const int csel = (lane >> 4) * 8;
    const uint32_t a_base = sbase + (uint32_t)((warp_m + rsel) * PAD + csel) * 2;
    const uint32_t b_base = sbase + A_BYTES + (uint32_t)((warp_n + rsel) * PAD + csel) * 2;

    auto issue = [&](int kt, int st) {
        uint32_t sa = sbase + st * STGB;
#pragma unroll
        for (int i = 0; i < 2; i++) {                      // A: 1024 int4
            int idx = tid + i * 512;
            int r = idx >> 2, c = idx & 3;
            const __half* ga = g_Ah + (size_t)(bm + r) * KE + kt * BK + c * 8;
            asm volatile("cp.async.cg.shared.global [%0], [%1], 16;"
                :: "r"(sa + (uint32_t)(r * PAD + c * 8) * 2), "l"(ga));
        }
        {                                                  // B: 512 int4
            uint32_t sb = sbase + st * STGB + A_BYTES;
            int r = tid >> 2, c = tid & 3;
            const __half* gb = g_Bh + (size_t)(bn + r) * KE + kt * BK + c * 8;
            asm volatile("cp.async.cg.shared.global [%0], [%1], 16;"
                :: "r"(sb + (uint32_t)(r * PAD + c * 8) * 2), "l"(gb));
        }
        asm volatile("cp.async.commit_group;" ::: "memory");
    };

    issue(0, 0); issue(1, 1);
    for (int kt = 0; kt < NKT; kt++) {
        int st = kt % NSTAGE;
        if (kt + 1 < NKT) {
            asm volatile("cp.async.wait_group 1;" ::: "memory");
        } else {
            asm volatile("cp.async.wait_group 0;" ::: "memory");
        }
        __syncthreads();
        if (kt + 2 < NKT) issue(kt + 2, (kt + 2) % NSTAGE);
        uint32_t ab = a_base + st * STGB;
        uint32_t bb = b_base + st * STGB;
#pragma unroll
        for (int ks = 0; ks < BK; ks += 16) {
            uint32_t afr[4][4], bfr[2][4];
#pragma unroll
            for (int im = 0; im < 4; im++)
                LDSM_X4(afr[im], ab + (uint32_t)(im * 16 * PAD + ks) * 2);
#pragma unroll
            for (int ip = 0; ip < 2; ip++)
                LDSM_X4(bfr[ip], bb + (uint32_t)(ip * 16 * PAD + ks) * 2);
#pragma unroll
            for (int im = 0; im < 4; im++)
#pragma unroll
                for (int ip = 0; ip < 2; ip++) {
                    asm volatile(
                        "mma.sync.aligned.m16n8k16.row.col.f32.f16.f16.f32 "
                        "{%0,%1,%2,%3}, {%4,%5,%6,%7}, {%8,%9}, {%0,%1,%2,%3};"
                        : "+f"(acc[im][2 * ip][0]), "+f"(acc[im][2 * ip][1]),
                          "+f"(acc[im][2 * ip][2]), "+f"(acc[im][2 * ip][3])
                        : "r"(afr[im][0]), "r"(afr[im][1]), "r"(afr[im][2]), "r"(afr[im][3]),
                          "r"(bfr[ip][0]), "r"(bfr[ip][2]));
                    asm volatile(
                        "mma.sync.aligned.m16n8k16.row.col.f32.f16.f16.f32 "
                        "{%0,%1,%2,%3}, {%4,%5,%6,%7}, {%8,%9}, {%0,%1,%2,%3};"
                        : "+f"(acc[im][2 * ip + 1][0]), "+f"(acc[im][2 * ip + 1][1]),
                          "+f"(acc[im][2 * ip + 1][2]), "+f"(acc[im][2 * ip + 1][3])
                        : "r"(afr[im][0]), "r"(afr[im][1]), "r"(afr[im][2]), "r"(afr[im][3]),
                          "r"(bfr[ip][1]), "r"(bfr[ip][3]));
                }
        }
    }

    // epilogue: branchless per-lane gate select (col0&3: 0 -> i,f ; 2 -> o,z)
#pragma unroll
    for (int im = 0; im < 4; im++)
#pragma unroll
        for (int in = 0; in < 4; in++) {
            int row0 = bm + warp_m + im * 16 + grp;
            int col0 = bn + warp_n + in * 8 + tq * 2;      // even n'
            bool isIF = (col0 & 3) == 0;
            int h = col0 >> 2;
            float b0 = isIF ? bi[h] : bo[h];
            float b1 = isIF ? bfg[h] : bz[h];
#pragma unroll
            for (int hrow = 0; hrow < 2; hrow++) {
                int row = row0 + hrow * 8;
                float a0 = acc[im][in][hrow * 2 + 0] + b0;
                float a1 = acc[im][in][hrow * 2 + 1] + b1;
                float u0 = isIF ? fminf(fmaxf(a0, -20.f), 0.f) : -a0;
                float u1 = isIF ? fminf(fmaxf(a1, -20.f), 0.f)
                                : 2.f * fminf(fmaxf(a1, -15.f), 15.f);
                float E0 = __expf(u0);
                float E1 = __expf(u1);
                float o0 = isIF ? E0 : __fdividef(1.f, 1.f + E0);        // i | o
                float o1 = isIF ? E1 : __fdividef(E1 - 1.f, E1 + 1.f);   // f | z
                *reinterpret_cast<__half2*>(g_Gh + (size_t)row * NG + col0)
                    = __floats2half2_rn(o0, o1);
            }
        }
}

// -- fused scan: 512 thr = 16 h x 32 chunks; double-buffered 8-deep prefetch --
__global__ __launch_bounds__(512, 2) void xl_scan(float* __restrict__ out) {
    __shared__ float sP[NCH][17], sC[NCH][17], sN[NCH][17];   // ~6.5 KB
    const int hl = threadIdx.x & 15, ch = threadIdx.x >> 4;   // ch 0..31
    const int h = blockIdx.x * 16 + hl;
    const int b = blockIdx.y;
    const size_t row0 = (size_t)b * SSQ + (size_t)ch * LCH;
    const uint2* base = reinterpret_cast<const uint2*>(g_Gh) + row0 * HH + h;

    // ---- pass 1: chunk-local (P, C, N), batches of 8 with double buffer ----
    float P = 1.f, C = 0.f, N = 0.f;
    {
        uint2 buf[2][8];
#pragma unroll
        for (int i = 0; i < 8; i++) buf[0][i] = base[(size_t)i * HH];
#pragma unroll
        for (int bt = 0; bt < 16; bt++) {
            const int cur = bt & 1;
            if (bt + 1 < 16) {
#pragma unroll
                for (int i = 0; i < 8; i++)
                    buf[cur ^ 1][i] = base[(size_t)((bt + 1) * 8 + i) * HH];
            }
#pragma unroll
            for (int i = 0; i < 8; i++) {
                float2 if2 = __half22float2(*reinterpret_cast<const __half2*>(&buf[cur][i].x));
                float2 oz2 = __half22float2(*reinterpret_cast<const __half2*>(&buf[cur][i].y));
                C = if2.y * C + if2.x * oz2.y;
                N = if2.y * N + if2.x;
                P *= if2.y;
            }
        }
    }
    sP[ch][hl] = P; sC[ch][hl] = C; sN[ch][hl] = N;
    __syncthreads();

    // ---- Hillis-Steele inclusive affine scan over chunks (5 steps) ----
#pragma unroll
    for (int d = 1; d < NCH; d <<= 1) {
        float p2 = 0.f, c2 = 0.f, n2 = 0.f;
        bool act = (ch >= d);
        if (act) { p2 = sP[ch - d][hl]; c2 = sC[ch - d][hl]; n2 = sN[ch - d][hl]; }
        __syncthreads();
        if (act) {
            C = P * c2 + C;
            N = P * n2 + N;
            P = P * p2;
            sP[ch][hl] = P; sC[ch][hl] = C; sN[ch][hl] = N;
        }
        __syncthreads();
    }

    // exclusive init for this chunk applied to (c0,n0) = (0,1)
    float c = 0.f, n = 1.f;
    if (ch > 0) {
        c = sC[ch - 1][hl];
        n = sN[ch - 1][hl] + sP[ch - 1][hl];
    }

    // ---- pass 3: recompute with init, emit h (same prefetch structure) ----
    float* ob = out + row0 * HH + h;
    {
        uint2 buf[2][8];
#pragma unroll
        for (int i = 0; i < 8; i++) buf[0][i] = base[(size_t)i * HH];
#pragma unroll
        for (int bt = 0; bt < 16; bt++) {
            const int cur = bt & 1;
            if (bt + 1 < 16) {
#pragma unroll
                for (int i = 0; i < 8; i++)
                    buf[cur ^ 1][i] = base[(size_t)((bt + 1) * 8 + i) * HH];
            }
#pragma unroll
            for (int i = 0; i < 8; i++) {
                float2 if2 = __half22float2(*reinterpret_cast<const __half2*>(&buf[cur][i].x));
                float2 oz2 = __half22float2(*reinterpret_cast<const __half2*>(&buf[cur][i].y));
                c = if2.y * c + if2.x * oz2.y;
                n = if2.y * n + if2.x;
                ob[(size_t)(bt * 8 + i) * HH] = oz2.x * (c / (n + EPSF));
            }
        }
    }
}

extern "C" void kernel_launch(void* const* d_in, const int* in_sizes, int n_in,
                              void* d_out, int out_size) {
    const float* x  = (const float*)d_in[0];
    const float* Wi = (const float*)d_in[1];
    const float* bi = (const float*)d_in[2];
    const float* Wf = (const float*)d_in[3];
    const float* bf = (const float*)d_in[4];
    const float* Wo = (const float*)d_in[5];
    const float* bo = (const float*)d_in[6];
    const float* Wz = (const float*)d_in[7];
    const float* bz = (const float*)d_in[8];
    float* out = (float*)d_out;

    cudaFuncSetAttribute(xl_gemm, cudaFuncAttributeMaxDynamicSharedMemorySize, SMEM_DYN);

    xl_prepA<<<(M * 64) / 256, 256>>>(x);
    xl_prepB<<<(NG * 64) / 256, 256>>>(Wi, Wf, Wo, Wz);
    xl_gemm<<<dim3(NG / BN, M / BM), 512, SMEM_DYN>>>(bi, bf, bo, bz);
    xl_scan<<<dim3(HH / 16, BB), 512>>>(out);
}

// round 14
// speedup vs baseline: 1.0610x; 1.0610x over previous
#include <cuda_runtime.h>
#include <cuda_fp16.h>
#include <cstdint>
#include <cstddef>

static constexpr int BB = 8, SSQ = 4096, DIN = 256, HH = 512;
static constexpr int M = BB * SSQ;        // 32768
static constexpr int KE = 256;            // single fp16 term
static constexpr int NG = 4 * HH;         // 2048
static constexpr float EPSF = 1e-6f;
static constexpr int LCH = 128, NCH = SSQ / LCH;   // 32 chunks of 128

static constexpr int PAD = 40;            // smem row stride (halfs); LDSM conflict-free
static constexpr int BM = 128, BN = 128, BK = 32;
static constexpr int NKT = KE / BK;       // 8
static constexpr int A_BYTES = BM * PAD * 2;   // 10240
static constexpr int B_BYTES = BN * PAD * 2;   // 10240
static constexpr int STGB = A_BYTES + B_BYTES; // 20480
static constexpr int NSTAGE = 4;
static constexpr int SMEM_DYN = NSTAGE * STGB; // 81920
static constexpr int SGT = 136;           // epilogue staging stride (halfs)

static __device__ __half g_Ah[(size_t)M * KE];     // 16 MB
static __device__ __half g_Bh[(size_t)NG * KE];    // 1 MB
// gates, gate-interleaved: element (m, h) = 4 halfs (i,f,o,z) at g_Gh[m*NG + h*4]
static __device__ __half g_Gh[(size_t)M * NG];     // 128 MB

__device__ __forceinline__ uint32_t smem_u32(const void* p) {
    uint32_t a;
    asm("{ .reg .u64 t; cvta.to.shared.u64 t, %1; cvt.u32.u64 %0, t; }" : "=r"(a) : "l"(p));
    return a;
}

// ---------------- prep A: fp16(x), row-major K-contig ----------------
__global__ void xl_prepA(const float* __restrict__ x) {
    int gid = blockIdx.x * blockDim.x + threadIdx.x;       // M*64 threads, 4 k each
    int j = gid & 63, m = gid >> 6;
    int k = j * 4;
    float4 v = *reinterpret_cast<const float4*>(x + (size_t)m * DIN + k);
    __half h[4] = {__float2half_rn(v.x), __float2half_rn(v.y),
                   __float2half_rn(v.z), __float2half_rn(v.w)};
    *reinterpret_cast<uint2*>(g_Ah + (size_t)m * KE + k) = *reinterpret_cast<uint2*>(h);
}

// ------- prep B: row n' = h*4 + gate; fp16(W) -------
__global__ void xl_prepB(const float* __restrict__ Wi, const float* __restrict__ Wf,
                         const float* __restrict__ Wo, const float* __restrict__ Wz) {
    int gid = blockIdx.x * blockDim.x + threadIdx.x;       // NG*64 threads, 4 k each
    int j = gid & 63, n = gid >> 6;
    int k = j * 4;
    int g = n & 3, h = n >> 2;
    const float* W = (g == 0) ? Wi : (g == 1) ? Wf : (g == 2) ? Wo : Wz;
    __half out[4];
#pragma unroll
    for (int t = 0; t < 4; t++)
        out[t] = __float2half_rn(W[(size_t)(k + t) * HH + h]);
    *reinterpret_cast<uint2*>(g_Bh + (size_t)n * KE + k) = *reinterpret_cast<uint2*>(out);
}

// ---------------- GEMM (ldmatrix + 4-stage cp.async) + staged epilogue ------
#define LDSM_X4(r, addr) \
    asm volatile("ldmatrix.sync.aligned.m8n8.x4.shared.b16 {%0,%1,%2,%3}, [%4];" \
        : "=r"((r)[0]), "=r"((r)[1]), "=r"((r)[2]), "=r"((r)[3]) : "r"(addr))

__global__ __launch_bounds__(256, 2) void xl_gemm(const float* __restrict__ bi, const float* __restrict__ bfg,
                                                  const float* __restrict__ bo, const float* __restrict__ bz) {
    extern __shared__ char smem[];
    const uint32_t sbase = smem_u32(smem);
    const int tid = threadIdx.x, lane = tid & 31, wid = tid >> 5;
    const int bm = blockIdx.y * BM, bn = blockIdx.x * BN;
    const int warp_m = (wid & 1) * 64, warp_n = (wid >> 1) * 32;
    const int grp = lane >> 2, tq = lane & 3;

    float acc[4][4][4];
#pragma unroll
    for (int a = 0; a < 4; a++)
#pragma unroll
        for (int b = 0; b < 4; b++)
#pragma unroll
            for (int c = 0; c < 4; c++) acc[a][b][c] = 0.f;

    const int rsel = (lane & 7) + ((lane >> 3) & 1) * 8;
    const int csel = (lane >> 4) * 8;
    const uint32_t a_base = sbase + (uint32_t)((warp_m + rsel) * PAD + csel) * 2;
    const uint32_t b_base = sbase + A_BYTES + (uint32_t)((warp_n + rsel) * PAD + csel) * 2;

    auto issue = [&](int kt, int st) {
        uint32_t sa = sbase + st * STGB;
#pragma unroll
        for (int i = 0; i < 2; i++) {                      // A: 512 int4
            int idx = tid + i * 256;
            int r = idx >> 2, c = idx & 3;
            const __half* ga = g_Ah + (size_t)(bm + r) * KE + kt * BK + c * 8;
            asm volatile("cp.async.cg.shared.global [%0], [%1], 16;"
                :: "r"(sa + (uint32_t)(r * PAD + c * 8) * 2), "l"(ga));
        }
        uint32_t sb = sbase + st * STGB + A_BYTES;
#pragma unroll
        for (int i = 0; i < 2; i++) {                      // B: 512 int4
            int idx = tid + i * 256;
            int r = idx >> 2, c = idx & 3;
            const __half* gb = g_Bh + (size_t)(bn + r) * KE + kt * BK + c * 8;
            asm volatile("cp.async.cg.shared.global [%0], [%1], 16;"
                :: "r"(sb + (uint32_t)(r * PAD + c * 8) * 2), "l"(gb));
        }
        asm volatile("cp.async.commit_group;" ::: "memory");
    };

    issue(0, 0); issue(1, 1); issue(2, 2);
    for (int kt = 0; kt < NKT; kt++) {
        int st = kt & 3;
        if (kt + 3 < NKT) {
            issue(kt + 3, (kt + 3) & 3);
            asm volatile("cp.async.wait_group 3;" ::: "memory");
        } else {
            asm volatile("cp.async.wait_group 0;" ::: "memory");
        }
        __syncthreads();
        uint32_t ab = a_base + st * STGB;
        uint32_t bb = b_base + st * STGB;
#pragma unroll
        for (int ks = 0; ks < BK; ks += 16) {
            uint32_t afr[4][4], bfr[2][4];
#pragma unroll
            for (int im = 0; im < 4; im++)
                LDSM_X4(afr[im], ab + (uint32_t)(im * 16 * PAD + ks) * 2);
#pragma unroll
            for (int ip = 0; ip < 2; ip++)
                LDSM_X4(bfr[ip], bb + (uint32_t)(ip * 16 * PAD + ks) * 2);
#pragma unroll
            for (int im = 0; im < 4; im++)
#pragma unroll
                for (int ip = 0; ip < 2; ip++) {
                    asm volatile(
                        "mma.sync.aligned.m16n8k16.row.col.f32.f16.f16.f32 "
                        "{%0,%1,%2,%3}, {%4,%5,%6,%7}, {%8,%9}, {%0,%1,%2,%3};"
                        : "+f"(acc[im][2 * ip][0]), "+f"(acc[im][2 * ip][1]),
                          "+f"(acc[im][2 * ip][2]), "+f"(acc[im][2 * ip][3])
                        : "r"(afr[im][0]), "r"(afr[im][1]), "r"(afr[im][2]), "r"(afr[im][3]),
                          "r"(bfr[ip][0]), "r"(bfr[ip][2]));
                    asm volatile(
                        "mma.sync.aligned.m16n8k16.row.col.f32.f16.f16.f32 "
                        "{%0,%1,%2,%3}, {%4,%5,%6,%7}, {%8,%9}, {%0,%1,%2,%3};"
                        : "+f"(acc[im][2 * ip + 1][0]), "+f"(acc[im][2 * ip + 1][1]),
                          "+f"(acc[im][2 * ip + 1][2]), "+f"(acc[im][2 * ip + 1][3])
                        : "r"(afr[im][0]), "r"(afr[im][1]), "r"(afr[im][2]), "r"(afr[im][3]),
                          "r"(bfr[ip][1]), "r"(bfr[ip][3]));
                }
        }
        __syncthreads();
    }

    // ---- epilogue: activate into smem staging, then coalesced uint4 stores --
    __half* sg = reinterpret_cast<__half*>(smem);   // 128 x SGT halfs = 34816 B
#pragma unroll
    for (int im = 0; im < 4; im++)
#pragma unroll
        for (int in = 0; in < 4; in++) {
            int row0 = warp_m + im * 16 + grp;             // local row
            int col0 = bn + warp_n + in * 8 + tq * 2;      // global even n'
            int colL = col0 - bn;
            bool isIF = (col0 & 3) == 0;
            int h = col0 >> 2;
            float b0 = isIF ? bi[h] : bo[h];
            float b1 = isIF ? bfg[h] : bz[h];
#pragma unroll
            for (int hrow = 0; hrow < 2; hrow++) {
                int row = row0 + hrow * 8;
                float a0 = acc[im][in][hrow * 2 + 0] + b0;
                float a1 = acc[im][in][hrow * 2 + 1] + b1;
                float u0 = isIF ? fminf(fmaxf(a0, -20.f), 0.f) : -a0;
                float u1 = isIF ? fminf(fmaxf(a1, -20.f), 0.f)
                                : 2.f * fminf(fmaxf(a1, -15.f), 15.f);
                float E0 = __expf(u0);
                float E1 = __expf(u1);
                float o0 = isIF ? E0 : __fdividef(1.f, 1.f + E0);        // i | o
                float o1 = isIF ? E1 : __fdividef(E1 - 1.f, E1 + 1.f);   // f | z
                *reinterpret_cast<__half2*>(sg + row * SGT + colL)
                    = __floats2half2_rn(o0, o1);
            }
        }
    __syncthreads();
    // copy out: 128 rows x 256 B, 16 threads per row, fully coalesced
#pragma unroll
    for (int i = 0; i < 8; i++) {
        int idx = tid + i * 256;
        int r = idx >> 4, c = idx & 15;
        *reinterpret_cast<uint4*>(g_Gh + (size_t)(bm + r) * NG + bn + c * 8)
            = *reinterpret_cast<const uint4*>(sg + r * SGT + c * 8);
    }
}

// -- fused scan: 512 thr = 16 h x 32 chunks; double-buffered 8-deep prefetch --
__global__ __launch_bounds__(512, 2) void xl_scan(float* __restrict__ out) {
    __shared__ float sP[NCH][17], sC[NCH][17], sN[NCH][17];   // ~6.5 KB
    const int hl = threadIdx.x & 15, ch = threadIdx.x >> 4;   // ch 0..31
    const int h = blockIdx.x * 16 + hl;
    const int b = blockIdx.y;
    const size_t row0 = (size_t)b * SSQ + (size_t)ch * LCH;
    const uint2* base = reinterpret_cast<const uint2*>(g_Gh) + row0 * HH + h;

    // ---- pass 1: chunk-local (P, C, N), batches of 8 with double buffer ----
    float P = 1.f, C = 0.f, N = 0.f;
    {
        uint2 buf[2][8];
#pragma unroll
        for (int i = 0; i < 8; i++) buf[0][i] = base[(size_t)i * HH];
#pragma unroll
        for (int bt = 0; bt < 16; bt++) {
            const int cur = bt & 1;
            if (bt + 1 < 16) {
#pragma unroll
                for (int i = 0; i < 8; i++)
                    buf[cur ^ 1][i] = base[(size_t)((bt + 1) * 8 + i) * HH];
            }
#pragma unroll
            for (int i = 0; i < 8; i++) {
                float2 if2 = __half22float2(*reinterpret_cast<const __half2*>(&buf[cur][i].x));
                float2 oz2 = __half22float2(*reinterpret_cast<const __half2*>(&buf[cur][i].y));
                C = if2.y * C + if2.x * oz2.y;
                N = if2.y * N + if2.x;
                P *= if2.y;
            }
        }
    }
    sP[ch][hl] = P; sC[ch][hl] = C; sN[ch][hl] = N;
    __syncthreads();

    // ---- Hillis-Steele inclusive affine scan over chunks (5 steps) ----
#pragma unroll
    for (int d = 1; d < NCH; d <<= 1) {
        float p2 = 0.f, c2 = 0.f, n2 = 0.f;
        bool act = (ch >= d);
        if (act) { p2 = sP[ch - d][hl]; c2 = sC[ch - d][hl]; n2 = sN[ch - d][hl]; }
        __syncthreads();
        if (act) {
            C = P * c2 + C;
            N = P * n2 + N;
            P = P * p2;
            sP[ch][hl] = P; sC[ch][hl] = C; sN[ch][hl] = N;
        }
        __syncthreads();
    }

    // exclusive init for this chunk applied to (c0,n0) = (0,1)
    float c = 0.f, n = 1.f;
    if (ch > 0) {
        c = sC[ch - 1][hl];
        n = sN[ch - 1][hl] + sP[ch - 1][hl];
    }

    // ---- pass 3: recompute with init, emit h (same prefetch structure) ----
    float* ob = out + row0 * HH + h;
    {
        uint2 buf[2][8];
#pragma unroll
        for (int i = 0; i < 8; i++) buf[0][i] = base[(size_t)i * HH];
#pragma unroll
        for (int bt = 0; bt < 16; bt++) {
            const int cur = bt & 1;
            if (bt + 1 < 16) {
#pragma unroll
                for (int i = 0; i < 8; i++)
                    buf[cur ^ 1][i] = base[(size_t)((bt + 1) * 8 + i) * HH];
            }
#pragma unroll
            for (int i = 0; i < 8; i++) {
                float2 if2 = __half22float2(*reinterpret_cast<const __half2*>(&buf[cur][i].x));
                float2 oz2 = __half22float2(*reinterpret_cast<const __half2*>(&buf[cur][i].y));
                c = if2.y * c + if2.x * oz2.y;
                n = if2.y * n + if2.x;
                ob[(size_t)(bt * 8 + i) * HH] = oz2.x * (c / (n + EPSF));
            }
        }
    }
}

extern "C" void kernel_launch(void* const* d_in, const int* in_sizes, int n_in,
                              void* d_out, int out_size) {
    const float* x  = (const float*)d_in[0];
    const float* Wi = (const float*)d_in[1];
    const float* bi = (const float*)d_in[2];
    const float* Wf = (const float*)d_in[3];
    const float* bf = (const float*)d_in[4];
    const float* Wo = (const float*)d_in[5];
    const float* bo = (const float*)d_in[6];
    const float* Wz = (const float*)d_in[7];
    const float* bz = (const float*)d_in[8];
    float* out = (float*)d_out;

    cudaFuncSetAttribute(xl_gemm, cudaFuncAttributeMaxDynamicSharedMemorySize, SMEM_DYN);

    xl_prepA<<<(M * 64) / 256, 256>>>(x);
    xl_prepB<<<(NG * 64) / 256, 256>>>(Wi, Wf, Wo, Wz);
    xl_gemm<<<dim3(NG / BN, M / BM), 256, SMEM_DYN>>>(bi, bf, bo, bz);
    xl_scan<<<dim3(HH / 16, BB), 512>>>(out);
}

// round 15
// speedup vs baseline: 1.0918x; 1.0290x over previous
#include <cuda_runtime.h>
#include <cuda_fp16.h>
#include <cstdint>
#include <cstddef>

static constexpr int BB = 8, SSQ = 4096, DIN = 256, HH = 512;
static constexpr int M = BB * SSQ;        // 32768
static constexpr int KE = 256;            // single fp16 term
static constexpr int NG = 4 * HH;         // 2048
static constexpr float EPSF = 1e-6f;
static constexpr int LCH = 128, NCH = SSQ / LCH;   // 32 chunks of 128

static constexpr int PAD = 40;            // smem row stride (halfs); LDSM conflict-free
static constexpr int BM = 128, BN = 128, BK = 32;
static constexpr int NKT = KE / BK;       // 8
static constexpr int A_BYTES = BM * PAD * 2;   // 10240
static constexpr int B_BYTES = BN * PAD * 2;   // 10240
static constexpr int STGB = A_BYTES + B_BYTES; // 20480
static constexpr int NSTAGE = 4;
static constexpr int SMEM_DYN = NSTAGE * STGB; // 81920
static constexpr int SGT = 136;           // epilogue staging stride (halfs)

static __device__ __half g_Ah[(size_t)M * KE];     // 16 MB
static __device__ __half g_Bh[(size_t)NG * KE];    // 1 MB
// gates, gate-interleaved: element (m, h) = 4 halfs (i,f,o,z) at g_Gh[m*NG + h*4]
static __device__ __half g_Gh[(size_t)M * NG];     // 128 MB

__device__ __forceinline__ uint32_t smem_u32(const void* p) {
    uint32_t a;
    asm("{ .reg .u64 t; cvta.to.shared.u64 t, %1; cvt.u32.u64 %0, t; }" : "=r"(a) : "l"(p));
    return a;
}

// ---------------- prep A: fp16(x), row-major K-contig ----------------
__global__ void xl_prepA(const float* __restrict__ x) {
    int gid = blockIdx.x * blockDim.x + threadIdx.x;       // M*64 threads, 4 k each
    int j = gid & 63, m = gid >> 6;
    int k = j * 4;
    float4 v = *reinterpret_cast<const float4*>(x + (size_t)m * DIN + k);
    __half h[4] = {__float2half_rn(v.x), __float2half_rn(v.y),
                   __float2half_rn(v.z), __float2half_rn(v.w)};
    *reinterpret_cast<uint2*>(g_Ah + (size_t)m * KE + k) = *reinterpret_cast<uint2*>(h);
}

// ------- prep B: row n' = h*4 + gate; fp16(W) -------
__global__ void xl_prepB(const float* __restrict__ Wi, const float* __restrict__ Wf,
                         const float* __restrict__ Wo, const float* __restrict__ Wz) {
    int gid = blockIdx.x * blockDim.x + threadIdx.x;       // NG*64 threads, 4 k each
    int j = gid & 63, n = gid >> 6;
    int k = j * 4;
    int g = n & 3, h = n >> 2;
    const float* W = (g == 0) ? Wi : (g == 1) ? Wf : (g == 2) ? Wo : Wz;
    __half out[4];
#pragma unroll
    for (int t = 0; t < 4; t++)
        out[t] = __float2half_rn(W[(size_t)(k + t) * HH + h]);
    *reinterpret_cast<uint2*>(g_Bh + (size_t)n * KE + k) = *reinterpret_cast<uint2*>(out);
}

// ------ GEMM (ldmatrix + 4-stage cp.async, single-sync) + staged epilogue ---
#define LDSM_X4(r, addr) \
    asm volatile("ldmatrix.sync.aligned.m8n8.x4.shared.b16 {%0,%1,%2,%3}, [%4];" \
        : "=r"((r)[0]), "=r"((r)[1]), "=r"((r)[2]), "=r"((r)[3]) : "r"(addr))

__global__ __launch_bounds__(256, 2) void xl_gemm(const float* __restrict__ bi, const float* __restrict__ bfg,
                                                  const float* __restrict__ bo, const float* __restrict__ bz) {
    extern __shared__ char smem[];
    const uint32_t sbase = smem_u32(smem);
    const int tid = threadIdx.x, lane = tid & 31, wid = tid >> 5;
    const int bm = blockIdx.y * BM, bn = blockIdx.x * BN;
    const int warp_m = (wid & 1) * 64, warp_n = (wid >> 1) * 32;
    const int grp = lane >> 2, tq = lane & 3;

    float acc[4][4][4];
#pragma unroll
    for (int a = 0; a < 4; a++)
#pragma unroll
        for (int b = 0; b < 4; b++)
#pragma unroll
            for (int c = 0; c < 4; c++) acc[a][b][c] = 0.f;

    const int rsel = (lane & 7) + ((lane >> 3) & 1) * 8;
    const int csel = (lane >> 4) * 8;
    const uint32_t a_base = sbase + (uint32_t)((warp_m + rsel) * PAD + csel) * 2;
    const uint32_t b_base = sbase + A_BYTES + (uint32_t)((warp_n + rsel) * PAD + csel) * 2;

    auto issue = [&](int kt, int st) {
        uint32_t sa = sbase + st * STGB;
#pragma unroll
        for (int i = 0; i < 2; i++) {                      // A: 512 int4
            int idx = tid + i * 256;
            int r = idx >> 2, c = idx & 3;
            const __half* ga = g_Ah + (size_t)(bm + r) * KE + kt * BK + c * 8;
            asm volatile("cp.async.cg.shared.global [%0], [%1], 16;"
                :: "r"(sa + (uint32_t)(r * PAD + c * 8) * 2), "l"(ga));
        }
        uint32_t sb = sbase + st * STGB + A_BYTES;
#pragma unroll
        for (int i = 0; i < 2; i++) {                      // B: 512 int4
            int idx = tid + i * 256;
            int r = idx >> 2, c = idx & 3;
            const __half* gb = g_Bh + (size_t)(bn + r) * KE + kt * BK + c * 8;
            asm volatile("cp.async.cg.shared.global [%0], [%1], 16;"
                :: "r"(sb + (uint32_t)(r * PAD + c * 8) * 2), "l"(gb));
        }
        asm volatile("cp.async.commit_group;" ::: "memory");
    };

    issue(0, 0); issue(1, 1); issue(2, 2);
    for (int kt = 0; kt < NKT; kt++) {
        int st = kt & 3;
        // stage kt ready when pending groups <= min(2, NKT-1-kt)
        if (kt <= NKT - 3) {
            asm volatile("cp.async.wait_group 2;" ::: "memory");
        } else if (kt == NKT - 2) {
            asm volatile("cp.async.wait_group 1;" ::: "memory");
        } else {
            asm volatile("cp.async.wait_group 0;" ::: "memory");
        }
        __syncthreads();
        if (kt + 3 < NKT) issue(kt + 3, (kt + 3) & 3);
        uint32_t ab = a_base + st * STGB;
        uint32_t bb = b_base + st * STGB;
#pragma unroll
        for (int ks = 0; ks < BK; ks += 16) {
            uint32_t afr[4][4], bfr[2][4];
#pragma unroll
            for (int im = 0; im < 4; im++)
                LDSM_X4(afr[im], ab + (uint32_t)(im * 16 * PAD + ks) * 2);
#pragma unroll
            for (int ip = 0; ip < 2; ip++)
                LDSM_X4(bfr[ip], bb + (uint32_t)(ip * 16 * PAD + ks) * 2);
#pragma unroll
            for (int im = 0; im < 4; im++)
#pragma unroll
                for (int ip = 0; ip < 2; ip++) {
                    asm volatile(
                        "mma.sync.aligned.m16n8k16.row.col.f32.f16.f16.f32 "
                        "{%0,%1,%2,%3}, {%4,%5,%6,%7}, {%8,%9}, {%0,%1,%2,%3};"
                        : "+f"(acc[im][2 * ip][0]), "+f"(acc[im][2 * ip][1]),
                          "+f"(acc[im][2 * ip][2]), "+f"(acc[im][2 * ip][3])
                        : "r"(afr[im][0]), "r"(afr[im][1]), "r"(afr[im][2]), "r"(afr[im][3]),
                          "r"(bfr[ip][0]), "r"(bfr[ip][2]));
                    asm volatile(
                        "mma.sync.aligned.m16n8k16.row.col.f32.f16.f16.f32 "
                        "{%0,%1,%2,%3}, {%4,%5,%6,%7}, {%8,%9}, {%0,%1,%2,%3};"
                        : "+f"(acc[im][2 * ip + 1][0]), "+f"(acc[im][2 * ip + 1][1]),
                          "+f"(acc[im][2 * ip + 1][2]), "+f"(acc[im][2 * ip + 1][3])
                        : "r"(afr[im][0]), "r"(afr[im][1]), "r"(afr[im][2]), "r"(afr[im][3]),
                          "r"(bfr[ip][1]), "r"(bfr[ip][3]));
                }
        }
    }
    __syncthreads();   // all compute done before staging reuses smem

    // ---- epilogue: activate into smem staging, then coalesced uint4 stores --
    __half* sg = reinterpret_cast<__half*>(smem);   // 128 x SGT halfs = 34816 B
#pragma unroll
    for (int im = 0; im < 4; im++)
#pragma unroll
        for (int in = 0; in < 4; in++) {
            int row0 = warp_m + im * 16 + grp;             // local row
            int col0 = bn + warp_n + in * 8 + tq * 2;      // global even n'
            int colL = col0 - bn;
            bool isIF = (col0 & 3) == 0;
            int h = col0 >> 2;
            float b0 = isIF ? bi[h] : bo[h];
            float b1 = isIF ? bfg[h] : bz[h];
#pragma unroll
            for (int hrow = 0; hrow < 2; hrow++) {
                int row = row0 + hrow * 8;
                float a0 = acc[im][in][hrow * 2 + 0] + b0;
                float a1 = acc[im][in][hrow * 2 + 1] + b1;
                float u0 = isIF ? fminf(fmaxf(a0, -20.f), 0.f) : -a0;
                float u1 = isIF ? fminf(fmaxf(a1, -20.f), 0.f)
                                : 2.f * fminf(fmaxf(a1, -15.f), 15.f);
                float E0 = __expf(u0);
                float E1 = __expf(u1);
                float o0 = isIF ? E0 : __fdividef(1.f, 1.f + E0);        // i | o
                float o1 = isIF ? E1 : __fdividef(E1 - 1.f, E1 + 1.f);   // f | z
                *reinterpret_cast<__half2*>(sg + row * SGT + colL)
                    = __floats2half2_rn(o0, o1);
            }
        }
    __syncthreads();
    // copy out: 128 rows x 256 B, 16 threads per row, fully coalesced
#pragma unroll
    for (int i = 0; i < 8; i++) {
        int idx = tid + i * 256;
        int r = idx >> 4, c = idx & 15;
        *reinterpret_cast<uint4*>(g_Gh + (size_t)(bm + r) * NG + bn + c * 8)
            = *reinterpret_cast<const uint4*>(sg + r * SGT + c * 8);
    }
}

// -- fused scan: 256 thr = 8 h x 32 chunks; grid 512 CTAs; 8-deep prefetch ----
__global__ __launch_bounds__(256, 4) void xl_scan(float* __restrict__ out) {
    __shared__ float sP[NCH][9], sC[NCH][9], sN[NCH][9];   // ~3.5 KB
    const int hl = threadIdx.x & 7, ch = threadIdx.x >> 3;   // ch 0..31
    const int h = blockIdx.x * 8 + hl;
    const int b = blockIdx.y;
    const size_t row0 = (size_t)b * SSQ + (size_t)ch * LCH;
    const uint2* base = reinterpret_cast<const uint2*>(g_Gh) + row0 * HH + h;

    // ---- pass 1: chunk-local (P, C, N), batches of 8 with double buffer ----
    float P = 1.f, C = 0.f, N = 0.f;
    {
        uint2 buf[2][8];
#pragma unroll
        for (int i = 0; i < 8; i++) buf[0][i] = base[(size_t)i * HH];
#pragma unroll
        for (int bt = 0; bt < 16; bt++) {
            const int cur = bt & 1;
            if (bt + 1 < 16) {
#pragma unroll
                for (int i = 0; i < 8; i++)
                    buf[cur ^ 1][i] = base[(size_t)((bt + 1) * 8 + i) * HH];
            }
#pragma unroll
            for (int i = 0; i < 8; i++) {
                float2 if2 = __half22float2(*reinterpret_cast<const __half2*>(&buf[cur][i].x));
                float2 oz2 = __half22float2(*reinterpret_cast<const __half2*>(&buf[cur][i].y));
                C = if2.y * C + if2.x * oz2.y;
                N = if2.y * N + if2.x;
                P *= if2.y;
            }
        }
    }
    sP[ch][hl] = P; sC[ch][hl] = C; sN[ch][hl] = N;
    __syncthreads();

    // ---- Hillis-Steele inclusive affine scan over chunks (5 steps) ----
#pragma unroll
    for (int d = 1; d < NCH; d <<= 1) {
        float p2 = 0.f, c2 = 0.f, n2 = 0.f;
        bool act = (ch >= d);
        if (act) { p2 = sP[ch - d][hl]; c2 = sC[ch - d][hl]; n2 = sN[ch - d][hl]; }
        __syncthreads();
        if (act) {
            C = P * c2 + C;
            N = P * n2 + N;
            P = P * p2;
            sP[ch][hl] = P; sC[ch][hl] = C; sN[ch][hl] = N;
        }
        __syncthreads();
    }

    // exclusive init for this chunk applied to (c0,n0) = (0,1)
    float c = 0.f, n = 1.f;
    if (ch > 0) {
        c = sC[ch - 1][hl];
        n = sN[ch - 1][hl] + sP[ch - 1][hl];
    }

    // ---- pass 3: recompute with init, emit h (same prefetch structure) ----
    float* ob = out + row0 * HH + h;
    {
        uint2 buf[2][8];
#pragma unroll
        for (int i = 0; i < 8; i++) buf[0][i] = base[(size_t)i * HH];
#pragma unroll
        for (int bt = 0; bt < 16; bt++) {
            const int cur = bt & 1;
            if (bt + 1 < 16) {
#pragma unroll
                for (int i = 0; i < 8; i++)
                    buf[cur ^ 1][i] = base[(size_t)((bt + 1) * 8 + i) * HH];
            }
#pragma unroll
            for (int i = 0; i < 8; i++) {
                float2 if2 = __half22float2(*reinterpret_cast<const __half2*>(&buf[cur][i].x));
                float2 oz2 = __half22float2(*reinterpret_cast<const __half2*>(&buf[cur][i].y));
                c = if2.y * c + if2.x * oz2.y;
                n = if2.y * n + if2.x;
                ob[(size_t)(bt * 8 + i) * HH] = oz2.x * (c / (n + EPSF));
            }
        }
    }
}

extern "C" void kernel_launch(void* const* d_in, const int* in_sizes, int n_in,
                              void* d_out, int out_size) {
    const float* x  = (const float*)d_in[0];
    const float* Wi = (const float*)d_in[1];
    const float* bi = (const float*)d_in[2];
    const float* Wf = (const float*)d_in[3];
    const float* bf = (const float*)d_in[4];
    const float* Wo = (const float*)d_in[5];
    const float* bo = (const float*)d_in[6];
    const float* Wz = (const float*)d_in[7];
    const float* bz = (const float*)d_in[8];
    float* out = (float*)d_out;

    cudaFuncSetAttribute(xl_gemm, cudaFuncAttributeMaxDynamicSharedMemorySize, SMEM_DYN);

    xl_prepA<<<(M * 64) / 256, 256>>>(x);
    xl_prepB<<<(NG * 64) / 256, 256>>>(Wi, Wf, Wo, Wz);
    xl_gemm<<<dim3(NG / BN, M / BM), 256, SMEM_DYN>>>(bi, bf, bo, bz);
    xl_scan<<<dim3(HH / 8, BB), 256>>>(out);
}

// round 16
// speedup vs baseline: 1.1413x; 1.0454x over previous
#include <cuda_runtime.h>
#include <cuda_fp16.h>
#include <cstdint>
#include <cstddef>

static constexpr int BB = 8, SSQ = 4096, DIN = 256, HH = 512;
static constexpr int M = BB * SSQ;        // 32768
static constexpr int KE = 256;            // single fp16 term
static constexpr int NG = 4 * HH;         // 2048
static constexpr float EPSF = 1e-6f;
static constexpr int LCH = 128, NCH = SSQ / LCH;   // 32 chunks of 128

static constexpr int PAD = 40;            // smem row stride (halfs); LDSM conflict-free
static constexpr int BM = 128, BN = 128, BK = 32;
static constexpr int NKT = KE / BK;       // 8
static constexpr int A_BYTES = BM * PAD * 2;   // 10240
static constexpr int B_BYTES = BN * PAD * 2;   // 10240
static constexpr int STGB = A_BYTES + B_BYTES; // 20480
static constexpr int NSTAGE = 4;
static constexpr int SMEM_DYN = NSTAGE * STGB; // 81920
static constexpr int SGT = 136;           // epilogue staging stride (halfs)

static __device__ __half g_Ah[(size_t)M * KE];     // 16 MB
static __device__ __half g_Bh[(size_t)NG * KE];    // 1 MB
// gates, gate-interleaved: element (m, h) = 4 halfs (i,f,o,z) at g_Gh[m*NG + h*4]
static __device__ __half g_Gh[(size_t)M * NG];     // 128 MB

__device__ __forceinline__ uint32_t smem_u32(const void* p) {
    uint32_t a;
    asm("{ .reg .u64 t; cvta.to.shared.u64 t, %1; cvt.u32.u64 %0, t; }" : "=r"(a) : "l"(p));
    return a;
}

// ------- fused prep: A = fp16(x); B row n' = h*4 + gate, fp16(W) -------
static constexpr int PREPA_THREADS = M * 64;       // 2,097,152
static constexpr int PREPB_THREADS = NG * 64;      // 131,072
__global__ void xl_prep(const float* __restrict__ x,
                        const float* __restrict__ Wi, const float* __restrict__ Wf,
                        const float* __restrict__ Wo, const float* __restrict__ Wz) {
    int gid = blockIdx.x * blockDim.x + threadIdx.x;
    if (gid < PREPA_THREADS) {
        int j = gid & 63, m = gid >> 6;
        int k = j * 4;
        float4 v = *reinterpret_cast<const float4*>(x + (size_t)m * DIN + k);
        __half h[4] = {__float2half_rn(v.x), __float2half_rn(v.y),
                       __float2half_rn(v.z), __float2half_rn(v.w)};
        *reinterpret_cast<uint2*>(g_Ah + (size_t)m * KE + k) = *reinterpret_cast<uint2*>(h);
    } else {
        int t2 = gid - PREPA_THREADS;
        if (t2 < PREPB_THREADS) {
            int j = t2 & 63, n = t2 >> 6;
            int k = j * 4;
            int g = n & 3, h = n >> 2;
            const float* W = (g == 0) ? Wi : (g == 1) ? Wf : (g == 2) ? Wo : Wz;
            __half out[4];
#pragma unroll
            for (int t = 0; t < 4; t++)
                out[t] = __float2half_rn(W[(size_t)(k + t) * HH + h]);
            *reinterpret_cast<uint2*>(g_Bh + (size_t)n * KE + k) = *reinterpret_cast<uint2*>(out);
        }
    }
}

// ------ GEMM (ldmatrix + 4-stage cp.async, single-sync) + staged epilogue ---
#define LDSM_X4(r, addr) \
    asm volatile("ldmatrix.sync.aligned.m8n8.x4.shared.b16 {%0,%1,%2,%3}, [%4];" \
        : "=r"((r)[0]), "=r"((r)[1]), "=r"((r)[2]), "=r"((r)[3]) : "r"(addr))

__global__ __launch_bounds__(256, 2) void xl_gemm(const float* __restrict__ bi, const float* __restrict__ bfg,
                                                  const float* __restrict__ bo, const float* __restrict__ bz) {
    extern __shared__ char smem[];
    const uint32_t sbase = smem_u32(smem);
    const int tid = threadIdx.x, lane = tid & 31, wid = tid >> 5;
    const int bm = blockIdx.y * BM, bn = blockIdx.x * BN;
    const int warp_m = (wid & 1) * 64, warp_n = (wid >> 1) * 32;
    const int grp = lane >> 2, tq = lane & 3;

    float acc[4][4][4];
#pragma unroll
    for (int a = 0; a < 4; a++)
#pragma unroll
        for (int b = 0; b < 4; b++)
#pragma unroll
            for (int c = 0; c < 4; c++) acc[a][b][c] = 0.f;

    const int rsel = (lane & 7) + ((lane >> 3) & 1) * 8;
    const int csel = (lane >> 4) * 8;
    const uint32_t a_base = sbase + (uint32_t)((warp_m + rsel) * PAD + csel) * 2;
    const uint32_t b_base = sbase + A_BYTES + (uint32_t)((warp_n + rsel) * PAD + csel) * 2;

    auto issue = [&](int kt, int st) {
        uint32_t sa = sbase + st * STGB;
#pragma unroll
        for (int i = 0; i < 2; i++) {                      // A: 512 int4
            int idx = tid + i * 256;
            int r = idx >> 2, c = idx & 3;
            const __half* ga = g_Ah + (size_t)(bm + r) * KE + kt * BK + c * 8;
            asm volatile("cp.async.cg.shared.global [%0], [%1], 16;"
                :: "r"(sa + (uint32_t)(r * PAD + c * 8) * 2), "l"(ga));
        }
        uint32_t sb = sbase + st * STGB + A_BYTES;
#pragma unroll
        for (int i = 0; i < 2; i++) {                      // B: 512 int4
            int idx = tid + i * 256;
            int r = idx >> 2, c = idx & 3;
            const __half* gb = g_Bh + (size_t)(bn + r) * KE + kt * BK + c * 8;
            asm volatile("cp.async.cg.shared.global [%0], [%1], 16;"
                :: "r"(sb + (uint32_t)(r * PAD + c * 8) * 2), "l"(gb));
        }
        asm volatile("cp.async.commit_group;" ::: "memory");
    };

    issue(0, 0); issue(1, 1); issue(2, 2);
    for (int kt = 0; kt < NKT; kt++) {
        int st = kt & 3;
        if (kt <= NKT - 3) {
            asm volatile("cp.async.wait_group 2;" ::: "memory");
        } else if (kt == NKT - 2) {
            asm volatile("cp.async.wait_group 1;" ::: "memory");
        } else {
            asm volatile("cp.async.wait_group 0;" ::: "memory");
        }
        __syncthreads();
        if (kt + 3 < NKT) issue(kt + 3, (kt + 3) & 3);
        uint32_t ab = a_base + st * STGB;
        uint32_t bb = b_base + st * STGB;
#pragma unroll
        for (int ks = 0; ks < BK; ks += 16) {
            uint32_t afr[4][4], bfr[2][4];
#pragma unroll
            for (int im = 0; im < 4; im++)
                LDSM_X4(afr[im], ab + (uint32_t)(im * 16 * PAD + ks) * 2);
#pragma unroll
            for (int ip = 0; ip < 2; ip++)
                LDSM_X4(bfr[ip], bb + (uint32_t)(ip * 16 * PAD + ks) * 2);
#pragma unroll
            for (int im = 0; im < 4; im++)
#pragma unroll
                for (int ip = 0; ip < 2; ip++) {
                    asm volatile(
                        "mma.sync.aligned.m16n8k16.row.col.f32.f16.f16.f32 "
                        "{%0,%1,%2,%3}, {%4,%5,%6,%7}, {%8,%9}, {%0,%1,%2,%3};"
                        : "+f"(acc[im][2 * ip][0]), "+f"(acc[im][2 * ip][1]),
                          "+f"(acc[im][2 * ip][2]), "+f"(acc[im][2 * ip][3])
                        : "r"(afr[im][0]), "r"(afr[im][1]), "r"(afr[im][2]), "r"(afr[im][3]),
                          "r"(bfr[ip][0]), "r"(bfr[ip][2]));
                    asm volatile(
                        "mma.sync.aligned.m16n8k16.row.col.f32.f16.f16.f32 "
                        "{%0,%1,%2,%3}, {%4,%5,%6,%7}, {%8,%9}, {%0,%1,%2,%3};"
                        : "+f"(acc[im][2 * ip + 1][0]), "+f"(acc[im][2 * ip + 1][1]),
                          "+f"(acc[im][2 * ip + 1][2]), "+f"(acc[im][2 * ip + 1][3])
                        : "r"(afr[im][0]), "r"(afr[im][1]), "r"(afr[im][2]), "r"(afr[im][3]),
                          "r"(bfr[ip][1]), "r"(bfr[ip][3]));
                }
        }
    }
    __syncthreads();   // all compute done before staging reuses smem

    // ---- epilogue: activate into smem staging, then coalesced uint4 stores --
    __half* sg = reinterpret_cast<__half*>(smem);   // 128 x SGT halfs = 34816 B
    // bias values are im-invariant: load the 8 needed once
    float bA[4], bBv[4];
    bool ifSel[4];
#pragma unroll
    for (int in = 0; in < 4; in++) {
        int col0 = bn + warp_n + in * 8 + tq * 2;
        bool isIF = (col0 & 3) == 0;
        int h = col0 >> 2;
        ifSel[in] = isIF;
        bA[in] = isIF ? bi[h] : bo[h];
        bBv[in] = isIF ? bfg[h] : bz[h];
    }
#pragma unroll
    for (int im = 0; im < 4; im++)
#pragma unroll
        for (int in = 0; in < 4; in++) {
            int row0 = warp_m + im * 16 + grp;             // local row
            int colL = warp_n + in * 8 + tq * 2;           // local col
            bool isIF = ifSel[in];
#pragma unroll
            for (int hrow = 0; hrow < 2; hrow++) {
                int row = row0 + hrow * 8;
                float a0 = acc[im][in][hrow * 2 + 0] + bA[in];
                float a1 = acc[im][in][hrow * 2 + 1] + bBv[in];
                float u0 = isIF ? fminf(fmaxf(a0, -20.f), 0.f) : -a0;
                float u1 = isIF ? fminf(fmaxf(a1, -20.f), 0.f)
                                : 2.f * fminf(fmaxf(a1, -15.f), 15.f);
                float E0 = __expf(u0);
                float E1 = __expf(u1);
                float o0 = isIF ? E0 : __fdividef(1.f, 1.f + E0);        // i | o
                float o1 = isIF ? E1 : __fdividef(E1 - 1.f, E1 + 1.f);   // f | z
                *reinterpret_cast<__half2*>(sg + row * SGT + colL)
                    = __floats2half2_rn(o0, o1);
            }
        }
    __syncthreads();
    // copy out: 128 rows x 256 B, 16 threads per row, fully coalesced
#pragma unroll
    for (int i = 0; i < 8; i++) {
        int idx = tid + i * 256;
        int r = idx >> 4, c = idx & 15;
        *reinterpret_cast<uint4*>(g_Gh + (size_t)(bm + r) * NG + bn + c * 8)
            = *reinterpret_cast<const uint4*>(sg + r * SGT + c * 8);
    }
}

// -- fused scan: 512 thr = 16 h x 32 chunks; double-buffered 8-deep prefetch --
__global__ __launch_bounds__(512, 2) void xl_scan(float* __restrict__ out) {
    __shared__ float sP[NCH][17], sC[NCH][17], sN[NCH][17];   // ~6.5 KB
    const int hl = threadIdx.x & 15, ch = threadIdx.x >> 4;   // ch 0..31
    const int h = blockIdx.x * 16 + hl;
    const int b = blockIdx.y;
    const size_t row0 = (size_t)b * SSQ + (size_t)ch * LCH;
    const uint2* base = reinterpret_cast<const uint2*>(g_Gh) + row0 * HH + h;

    // ---- pass 1: chunk-local (P, C, N), batches of 8 with double buffer ----
    float P = 1.f, C = 0.f, N = 0.f;
    {
        uint2 buf[2][8];
#pragma unroll
        for (int i = 0; i < 8; i++) buf[0][i] = base[(size_t)i * HH];
#pragma unroll
        for (int bt = 0; bt < 16; bt++) {
            const int cur = bt & 1;
            if (bt + 1 < 16) {
#pragma unroll
                for (int i = 0; i < 8; i++)
                    buf[cur ^ 1][i] = base[(size_t)((bt + 1) * 8 + i) * HH];
            }
#pragma unroll
            for (int i = 0; i < 8; i++) {
                float2 if2 = __half22float2(*reinterpret_cast<const __half2*>(&buf[cur][i].x));
                float2 oz2 = __half22float2(*reinterpret_cast<const __half2*>(&buf[cur][i].y));
                C = if2.y * C + if2.x * oz2.y;
                N = if2.y * N + if2.x;
                P *= if2.y;
            }
        }
    }
    sP[ch][hl] = P; sC[ch][hl] = C; sN[ch][hl] = N;
    __syncthreads();

    // ---- Hillis-Steele inclusive affine scan over chunks (5 steps) ----
#pragma unroll
    for (int d = 1; d < NCH; d <<= 1) {
        float p2 = 0.f, c2 = 0.f, n2 = 0.f;
        bool act = (ch >= d);
        if (act) { p2 = sP[ch - d][hl]; c2 = sC[ch - d][hl]; n2 = sN[ch - d][hl]; }
        __syncthreads();
        if (act) {
            C = P * c2 + C;
            N = P * n2 + N;
            P = P * p2;
            sP[ch][hl] = P; sC[ch][hl] = C; sN[ch][hl] = N;
        }
        __syncthreads();
    }

    // exclusive init for this chunk applied to (c0,n0) = (0,1)
    float c = 0.f, n = 1.f;
    if (ch > 0) {
        c = sC[ch - 1][hl];
        n = sN[ch - 1][hl] + sP[ch - 1][hl];
    }

    // ---- pass 3: recompute with init, emit h (same prefetch structure) ----
    float* ob = out + row0 * HH + h;
    {
        uint2 buf[2][8];
#pragma unroll
        for (int i = 0; i < 8; i++) buf[0][i] = base[(size_t)i * HH];
#pragma unroll
        for (int bt = 0; bt < 16; bt++) {
            const int cur = bt & 1;
            if (bt + 1 < 16) {
#pragma unroll
                for (int i = 0; i < 8; i++)
                    buf[cur ^ 1][i] = base[(size_t)((bt + 1) * 8 + i) * HH];
            }
#pragma unroll
            for (int i = 0; i < 8; i++) {
                float2 if2 = __half22float2(*reinterpret_cast<const __half2*>(&buf[cur][i].x));
                float2 oz2 = __half22float2(*reinterpret_cast<const __half2*>(&buf[cur][i].y));
                c = if2.y * c + if2.x * oz2.y;
                n = if2.y * n + if2.x;
                ob[(size_t)(bt * 8 + i) * HH] = oz2.x * (c / (n + EPSF));
            }
        }
    }
}

extern "C" void kernel_launch(void* const* d_in, const int* in_sizes, int n_in,
                              void* d_out, int out_size) {
    const float* x  = (const float*)d_in[0];
    const float* Wi = (const float*)d_in[1];
    const float* bi = (const float*)d_in[2];
    const float* Wf = (const float*)d_in[3];
    const float* bf = (const float*)d_in[4];
    const float* Wo = (const float*)d_in[5];
    const float* bo = (const float*)d_in[6];
    const float* Wz = (const float*)d_in[7];
    const float* bz = (const float*)d_in[8];
    float* out = (float*)d_out;

    cudaFuncSetAttribute(xl_gemm, cudaFuncAttributeMaxDynamicSharedMemorySize, SMEM_DYN);

    xl_prep<<<(PREPA_THREADS + PREPB_THREADS) / 256, 256>>>(x, Wi, Wf, Wo, Wz);
    xl_gemm<<<dim3(NG / BN, M / BM), 256, SMEM_DYN>>>(bi, bf, bo, bz);
    xl_scan<<<dim3(HH / 16, BB), 512>>>(out);
}